// round 3
// baseline (speedup 1.0000x reference)
#include <cuda_runtime.h>
#include <cuda_bf16.h>
#include <cstdint>

#define N_NODES 50000
#define N_EDGES 800000
#define D 128

// ---------------- device scratch (no allocations allowed) ----------------
__device__ float g_hneigh[(size_t)N_NODES * D];   // mean-aggregated neighbor feats
__device__ int   g_deg[N_NODES];
__device__ int   g_rowoff[N_NODES + 1];
__device__ int   g_cursor[N_NODES];
__device__ int   g_edgesrc[N_EDGES];
__device__ float g_WT[256 * D];                   // [k][c], k<128: Wself, k>=128: Wneigh
__device__ float g_bcat[D];                       // b_self + bias
__device__ int   g_is64;

// ---------------- index dtype detection ----------------
// If indices are int64 (little endian, values in [0,50000)), every odd 32-bit
// word is zero. For int32 data those words are random node ids (P(all 256
// zero) ~ (2e-5)^256 ~ 0). Deterministic given inputs.
__global__ void k_detect(const unsigned* p) {
    __shared__ unsigned s[256];
    s[threadIdx.x] = p[2 * threadIdx.x + 1];
    __syncthreads();
    for (int off = 128; off > 0; off >>= 1) {
        if (threadIdx.x < off) s[threadIdx.x] |= s[threadIdx.x + off];
        __syncthreads();
    }
    if (threadIdx.x == 0) g_is64 = (s[0] == 0) ? 1 : 0;
}

__device__ __forceinline__ int edge_idx(const void* p, int i, int is64) {
    return is64 ? (int)((const long long*)p)[i] : ((const int*)p)[i];
}

// ---------------- prep: zero counters, build transposed W and fused bias ----
__global__ void k_prep(const float* __restrict__ Wself, const float* __restrict__ bself,
                       const float* __restrict__ Wneigh, const float* __restrict__ bias) {
    int i = blockIdx.x * blockDim.x + threadIdx.x;
    if (i < N_NODES) { g_deg[i] = 0; g_cursor[i] = 0; }
    if (i < D * D) {
        int k = i >> 7, c = i & 127;           // i = k*128 + c
        g_WT[i]          = Wself [c * D + k];  // WT[k][c] = W[c][k]
        g_WT[D * D + i]  = Wneigh[c * D + k];
    }
    if (i < D) g_bcat[i] = bself[i] + bias[i];
}

// ---------------- CSR build ----------------
__global__ void k_hist(const void* __restrict__ dst) {
    int e = blockIdx.x * blockDim.x + threadIdx.x;
    if (e < N_EDGES) {
        int d = edge_idx(dst, e, g_is64);
        atomicAdd(&g_deg[d], 1);
    }
}

// single-block exclusive scan of g_deg -> g_rowoff (50001 entries)
__global__ void k_scan() {
    __shared__ int warpsum[32];
    int t = threadIdx.x, lane = t & 31, w = t >> 5;
    int carry = 0;
    for (int base = 0; base < N_NODES; base += 1024) {
        int i = base + t;
        int v = (i < N_NODES) ? g_deg[i] : 0;
        int x = v;
        #pragma unroll
        for (int off = 1; off < 32; off <<= 1) {
            int y = __shfl_up_sync(0xffffffff, x, off);
            if (lane >= off) x += y;
        }
        if (lane == 31) warpsum[w] = x;
        __syncthreads();
        if (w == 0) {
            int s = warpsum[lane];
            #pragma unroll
            for (int off = 1; off < 32; off <<= 1) {
                int y = __shfl_up_sync(0xffffffff, s, off);
                if (lane >= off) s += y;
            }
            warpsum[lane] = s;
        }
        __syncthreads();
        int pre = (w > 0) ? warpsum[w - 1] : 0;
        int incl = x + pre;
        if (i < N_NODES) g_rowoff[i] = carry + incl - v;
        carry += warpsum[31];
        __syncthreads();   // protect warpsum for the next chunk
    }
    if (t == 0) g_rowoff[N_NODES] = carry;
}

__global__ void k_scatter(const void* __restrict__ src, const void* __restrict__ dst) {
    int e = blockIdx.x * blockDim.x + threadIdx.x;
    if (e < N_EDGES) {
        int is64 = g_is64;
        int d = edge_idx(dst, e, is64);
        int s = edge_idx(src, e, is64);
        int pos = g_rowoff[d] + atomicAdd(&g_cursor[d], 1);
        g_edgesrc[pos] = s;
    }
}

// ---------------- SpMM: warp per node, gather + mean ----------------
__global__ void k_spmm(const float* __restrict__ feat) {
    int g = (blockIdx.x * blockDim.x + threadIdx.x) >> 5;
    int lane = threadIdx.x & 31;
    if (g >= N_NODES) return;
    int beg = g_rowoff[g], end = g_rowoff[g + 1];
    float4 acc = make_float4(0.f, 0.f, 0.f, 0.f);
    int e = beg;
    // 4-way unroll for memory-level parallelism on the gathers
    for (; e + 3 < end; e += 4) {
        int s0 = g_edgesrc[e + 0], s1 = g_edgesrc[e + 1];
        int s2 = g_edgesrc[e + 2], s3 = g_edgesrc[e + 3];
        float4 f0 = *(const float4*)(feat + (size_t)s0 * D + lane * 4);
        float4 f1 = *(const float4*)(feat + (size_t)s1 * D + lane * 4);
        float4 f2 = *(const float4*)(feat + (size_t)s2 * D + lane * 4);
        float4 f3 = *(const float4*)(feat + (size_t)s3 * D + lane * 4);
        acc.x += f0.x + f1.x + f2.x + f3.x;
        acc.y += f0.y + f1.y + f2.y + f3.y;
        acc.z += f0.z + f1.z + f2.z + f3.z;
        acc.w += f0.w + f1.w + f2.w + f3.w;
    }
    for (; e < end; e++) {
        int s = g_edgesrc[e];
        float4 f = *(const float4*)(feat + (size_t)s * D + lane * 4);
        acc.x += f.x; acc.y += f.y; acc.z += f.z; acc.w += f.w;
    }
    float inv = (end > beg) ? 1.0f / (float)(end - beg) : 0.0f;
    acc.x *= inv; acc.y *= inv; acc.z *= inv; acc.w *= inv;
    *(float4*)(g_hneigh + (size_t)g * D + lane * 4) = acc;
}

// ---------------- fused GEMM: out = [feat | hneigh] @ WT + bcat ----------------
// Block: 256 threads (8 warps), 64 rows per block. All of WT (256x128, 128KB)
// plus the 64 X rows (64KB) live in SMEM. Each lane owns 8 rows x 4 cols:
// 32 FMA per LDS.128 of W -> FMA-pipe bound.
#define GROWS 64
__global__ void k_gemm(const float* __restrict__ feat, float* __restrict__ out) {
    extern __shared__ float smem[];
    float* sWT = smem;                 // 256*128 floats
    float* sX  = smem + 256 * D;       // 64*256 floats
    int tid = threadIdx.x, w = tid >> 5, lane = tid & 31;

    {   // load WT (coalesced float4 copy)
        const float4* gW4 = (const float4*)g_WT;
        float4* sW4 = (float4*)sWT;
        #pragma unroll
        for (int i = tid; i < 256 * 32; i += 256) sW4[i] = gW4[i];
    }
    int row0 = blockIdx.x * GROWS;
    for (int i = tid; i < GROWS * 256; i += 256) {
        int r = i >> 8, k = i & 255;
        int row = row0 + r;
        float v = 0.f;
        if (row < N_NODES)
            v = (k < D) ? feat[(size_t)row * D + k]
                        : g_hneigh[(size_t)row * D + (k - D)];
        sX[i] = v;
    }
    __syncthreads();

    float4 bv = ((const float4*)g_bcat)[lane];
    float4 acc[8];
    #pragma unroll
    for (int r = 0; r < 8; r++) acc[r] = bv;

    const float*  xb   = sX + (w * 8) * 256;
    const float4* sW4l = (const float4*)sWT;
    #pragma unroll 4
    for (int k = 0; k < 256; k++) {
        float4 wv = sW4l[k * 32 + lane];
        #pragma unroll
        for (int r = 0; r < 8; r++) {
            float xv = xb[r * 256 + k];
            acc[r].x += xv * wv.x;
            acc[r].y += xv * wv.y;
            acc[r].z += xv * wv.z;
            acc[r].w += xv * wv.w;
        }
    }

    #pragma unroll
    for (int r = 0; r < 8; r++) {
        int row = row0 + w * 8 + r;
        if (row < N_NODES)
            *(float4*)(out + (size_t)row * D + lane * 4) = acc[r];
    }
}

// ---------------- launcher ----------------
extern "C" void kernel_launch(void* const* d_in, const int* in_sizes, int n_in,
                              void* d_out, int out_size) {
    const float* feat   = (const float*)d_in[0];
    const void*  src    = d_in[1];
    const void*  dst    = d_in[2];
    const float* Wself  = (const float*)d_in[3];
    const float* bself  = (const float*)d_in[4];
    const float* Wneigh = (const float*)d_in[5];
    const float* bias   = (const float*)d_in[6];
    float* out = (float*)d_out;

    static_assert((256 * D + GROWS * 256) * sizeof(float) == 196608, "smem size");
    cudaFuncSetAttribute(k_gemm, cudaFuncAttributeMaxDynamicSharedMemorySize, 196608);

    k_detect<<<1, 256>>>((const unsigned*)src);
    k_prep<<<(N_NODES + 255) / 256, 256>>>(Wself, bself, Wneigh, bias);
    k_hist<<<(N_EDGES + 255) / 256, 256>>>(dst);
    k_scan<<<1, 1024>>>();
    k_scatter<<<(N_EDGES + 255) / 256, 256>>>(src, dst);
    k_spmm<<<(N_NODES * 32 + 255) / 256, 256>>>(feat);
    k_gemm<<<(N_NODES + GROWS - 1) / GROWS, 256, 196608>>>(feat, out);
}

// round 4
// speedup vs baseline: 1.0832x; 1.0832x over previous
#include <cuda_runtime.h>
#include <cuda_bf16.h>
#include <cstdint>

#define N_NODES 50000
#define N_EDGES 800000
#define D 128
#define SCAN_BLK 1024
#define NBLK ((N_NODES + SCAN_BLK - 1) / SCAN_BLK)   // 49

// ---------------- device scratch (no allocations allowed) ----------------
__device__ float g_hneigh[(size_t)N_NODES * D];
__device__ int   g_deg[N_NODES];
__device__ int   g_rowoff[N_NODES + 1];
__device__ int   g_cursor[N_NODES];
__device__ int   g_edgesrc[N_EDGES];
__device__ int   g_bsum[NBLK];
__device__ int   g_bpre[NBLK];
__device__ float g_WT[256 * D];     // [k][c]; k<128: Wself, k>=128: Wneigh
__device__ float g_bcat[D];         // b_self + bias
__device__ int   g_is64;

__device__ __forceinline__ int edge_idx(const void* p, int i, int is64) {
    return is64 ? (int)((const long long*)p)[i] : ((const int*)p)[i];
}

// packed fp32x2 helpers (sm_103a FFMA2 — PTX-only, ptxas never auto-fuses)
__device__ __forceinline__ unsigned long long ffma2(unsigned long long a,
                                                    unsigned long long b,
                                                    unsigned long long c) {
    unsigned long long d;
    asm("fma.rn.f32x2 %0, %1, %2, %3;" : "=l"(d) : "l"(a), "l"(b), "l"(c));
    return d;
}
__device__ __forceinline__ unsigned long long dup2(float x) {
    unsigned long long d;
    asm("mov.b64 %0, {%1, %1};" : "=l"(d) : "f"(x));
    return d;
}
__device__ __forceinline__ float2 unpk(unsigned long long v) {
    float2 r;
    asm("mov.b64 {%0, %1}, %2;" : "=f"(r.x), "=f"(r.y) : "l"(v));
    return r;
}

// ---------------- prep: detect idx dtype, zero counters, build WT, bias ----
// int64 indices in [0,50000) have all-zero odd 32-bit words; int32 node ids
// make P(256 words all zero) ~ 0. Deterministic for fixed inputs.
__global__ void k_prep(const float* __restrict__ Wself, const float* __restrict__ bself,
                       const float* __restrict__ Wneigh, const float* __restrict__ bias,
                       const unsigned* __restrict__ src_raw) {
    int i = blockIdx.x * blockDim.x + threadIdx.x;
    if (blockIdx.x == 0) {                       // whole block 0: uniform branch
        __shared__ unsigned sor[8];
        int t = threadIdx.x, lane = t & 31, w = t >> 5;
        unsigned v = src_raw[2 * t + 1];
        #pragma unroll
        for (int off = 16; off > 0; off >>= 1) v |= __shfl_xor_sync(0xffffffffu, v, off);
        if (lane == 0) sor[w] = v;
        __syncthreads();
        if (t == 0) {
            unsigned o = 0;
            #pragma unroll
            for (int j = 0; j < 8; j++) o |= sor[j];
            g_is64 = (o == 0) ? 1 : 0;
            g_rowoff[N_NODES] = N_EDGES;
        }
    }
    if (i < N_NODES) { g_deg[i] = 0; g_cursor[i] = 0; }
    if (i < D * D) {
        int k = i >> 7, c = i & 127;
        g_WT[i]         = Wself [c * D + k];
        g_WT[D * D + i] = Wneigh[c * D + k];
    }
    if (i < D) g_bcat[i] = bself[i] + bias[i];
}

// ---------------- CSR build ----------------
__global__ void k_hist(const void* __restrict__ dst) {
    int e = blockIdx.x * blockDim.x + threadIdx.x;
    if (e < N_EDGES) atomicAdd(&g_deg[edge_idx(dst, e, g_is64)], 1);
}

// 3-phase parallel exclusive scan of g_deg -> g_rowoff
__global__ void k_scan1() {
    __shared__ int wsum[32];
    int t = threadIdx.x, lane = t & 31, w = t >> 5;
    int i = blockIdx.x * SCAN_BLK + t;
    int v = (i < N_NODES) ? g_deg[i] : 0;
    int x = v;
    #pragma unroll
    for (int off = 1; off < 32; off <<= 1) {
        int y = __shfl_up_sync(0xffffffff, x, off);
        if (lane >= off) x += y;
    }
    if (lane == 31) wsum[w] = x;
    __syncthreads();
    if (w == 0) {
        int s = wsum[lane];
        #pragma unroll
        for (int off = 1; off < 32; off <<= 1) {
            int y = __shfl_up_sync(0xffffffff, s, off);
            if (lane >= off) s += y;
        }
        wsum[lane] = s;
    }
    __syncthreads();
    int pre = (w > 0) ? wsum[w - 1] : 0;
    if (i < N_NODES) g_rowoff[i] = x + pre - v;       // exclusive, local to block
    if (t == SCAN_BLK - 1) g_bsum[blockIdx.x] = x + pre;
}

__global__ void k_scan2() {                           // 64 threads, scan 49 partials
    __shared__ int ws[2];
    int t = threadIdx.x, lane = t & 31, w = t >> 5;
    int v = (t < NBLK) ? g_bsum[t] : 0;
    int x = v;
    #pragma unroll
    for (int off = 1; off < 32; off <<= 1) {
        int y = __shfl_up_sync(0xffffffff, x, off);
        if (lane >= off) x += y;
    }
    if (lane == 31) ws[w] = x;
    __syncthreads();
    if (w == 1) x += ws[0];
    if (t < NBLK) g_bpre[t] = x - v;                  // exclusive
}

__global__ void k_scan3() {
    int i = blockIdx.x * SCAN_BLK + threadIdx.x;
    if (i < N_NODES) g_rowoff[i] += g_bpre[blockIdx.x];
}

__global__ void k_scatter(const void* __restrict__ src, const void* __restrict__ dst) {
    int e = blockIdx.x * blockDim.x + threadIdx.x;
    if (e < N_EDGES) {
        int is64 = g_is64;
        int d = edge_idx(dst, e, is64);
        int s = edge_idx(src, e, is64);
        g_edgesrc[g_rowoff[d] + atomicAdd(&g_cursor[d], 1)] = s;
    }
}

// ---------------- SpMM: warp per node, gather + mean ----------------
__global__ void k_spmm(const float* __restrict__ feat) {
    int g = (blockIdx.x * blockDim.x + threadIdx.x) >> 5;
    int lane = threadIdx.x & 31;
    if (g >= N_NODES) return;
    int beg = g_rowoff[g], end = g_rowoff[g + 1];
    float4 acc = make_float4(0.f, 0.f, 0.f, 0.f);
    int e = beg;
    for (; e + 3 < end; e += 4) {
        int s0 = g_edgesrc[e + 0], s1 = g_edgesrc[e + 1];
        int s2 = g_edgesrc[e + 2], s3 = g_edgesrc[e + 3];
        float4 f0 = *(const float4*)(feat + (size_t)s0 * D + lane * 4);
        float4 f1 = *(const float4*)(feat + (size_t)s1 * D + lane * 4);
        float4 f2 = *(const float4*)(feat + (size_t)s2 * D + lane * 4);
        float4 f3 = *(const float4*)(feat + (size_t)s3 * D + lane * 4);
        acc.x += f0.x + f1.x + f2.x + f3.x;
        acc.y += f0.y + f1.y + f2.y + f3.y;
        acc.z += f0.z + f1.z + f2.z + f3.z;
        acc.w += f0.w + f1.w + f2.w + f3.w;
    }
    for (; e < end; e++) {
        int s = g_edgesrc[e];
        float4 f = *(const float4*)(feat + (size_t)s * D + lane * 4);
        acc.x += f.x; acc.y += f.y; acc.z += f.z; acc.w += f.w;
    }
    float inv = (end > beg) ? 1.0f / (float)(end - beg) : 0.0f;
    acc.x *= inv; acc.y *= inv; acc.z *= inv; acc.w *= inv;
    *(float4*)(g_hneigh + (size_t)g * D + lane * 4) = acc;
}

// ---------------- fused GEMM (FFMA2): out = [feat|hneigh] @ WT + bcat -------
// 256 threads / 8 warps / 64 rows per block. WT (128KB) + transposed X
// (256 x stride-66 floats, 66KB) in SMEM. Each lane: 4 row-pairs x 4 cols,
// 16 fma.rn.f32x2 per k = 32 FMA -> half the fma-pipe ops of scalar FFMA.
#define GROWS 64
#define XS 66                                       // 8B-aligned, <=2-way banks
#define GEMM_SMEM ((256 * D + 256 * XS) * sizeof(float))
__global__ void k_gemm(const float* __restrict__ feat, float* __restrict__ out) {
    extern __shared__ float smem[];
    float* sWT = smem;                              // 256*128
    float* sX  = smem + 256 * D;                    // [k][row], stride XS
    int tid = threadIdx.x, w = tid >> 5, lane = tid & 31;

    {   // WT: coalesced float4 copy
        const float4* gW4 = (const float4*)g_WT;
        float4* sW4 = (float4*)sWT;
        #pragma unroll
        for (int i = tid; i < 256 * 32; i += 256) sW4[i] = gW4[i];
    }
    int row0 = blockIdx.x * GROWS;
    for (int i = tid; i < GROWS * 256; i += 256) {  // coalesced global reads
        int r = i >> 8, k = i & 255;
        int row = row0 + r;
        float v = 0.f;
        if (row < N_NODES)
            v = (k < D) ? feat[(size_t)row * D + k]
                        : g_hneigh[(size_t)row * D + (k - D)];
        sX[k * XS + r] = v;
    }
    __syncthreads();

    float4 bv = ((const float4*)g_bcat)[lane];
    unsigned long long acc[4][4];
    #pragma unroll
    for (int p = 0; p < 4; p++) {
        acc[p][0] = dup2(bv.x); acc[p][1] = dup2(bv.y);
        acc[p][2] = dup2(bv.z); acc[p][3] = dup2(bv.w);
    }

    const float4* sW4 = (const float4*)sWT;
    const float*  xb  = sX + w * 8;
    #pragma unroll 2
    for (int k = 0; k < 256; k++) {
        float4 wv = sW4[k * 32 + lane];
        unsigned long long w0 = dup2(wv.x), w1 = dup2(wv.y),
                           w2 = dup2(wv.z), w3 = dup2(wv.w);
        const float* xk = xb + k * XS;
        unsigned long long x0 = *(const unsigned long long*)(xk + 0);
        unsigned long long x1 = *(const unsigned long long*)(xk + 2);
        unsigned long long x2 = *(const unsigned long long*)(xk + 4);
        unsigned long long x3 = *(const unsigned long long*)(xk + 6);
        acc[0][0] = ffma2(x0, w0, acc[0][0]); acc[0][1] = ffma2(x0, w1, acc[0][1]);
        acc[0][2] = ffma2(x0, w2, acc[0][2]); acc[0][3] = ffma2(x0, w3, acc[0][3]);
        acc[1][0] = ffma2(x1, w0, acc[1][0]); acc[1][1] = ffma2(x1, w1, acc[1][1]);
        acc[1][2] = ffma2(x1, w2, acc[1][2]); acc[1][3] = ffma2(x1, w3, acc[1][3]);
        acc[2][0] = ffma2(x2, w0, acc[2][0]); acc[2][1] = ffma2(x2, w1, acc[2][1]);
        acc[2][2] = ffma2(x2, w2, acc[2][2]); acc[2][3] = ffma2(x2, w3, acc[2][3]);
        acc[3][0] = ffma2(x3, w0, acc[3][0]); acc[3][1] = ffma2(x3, w1, acc[3][1]);
        acc[3][2] = ffma2(x3, w2, acc[3][2]); acc[3][3] = ffma2(x3, w3, acc[3][3]);
    }

    #pragma unroll
    for (int p = 0; p < 4; p++) {
        float2 a0 = unpk(acc[p][0]), a1 = unpk(acc[p][1]);
        float2 a2 = unpk(acc[p][2]), a3 = unpk(acc[p][3]);
        int rlo = row0 + w * 8 + 2 * p;
        if (rlo < N_NODES) {
            float4 olo = make_float4(a0.x, a1.x, a2.x, a3.x);
            *(float4*)(out + (size_t)rlo * D + lane * 4) = olo;
        }
        if (rlo + 1 < N_NODES) {
            float4 ohi = make_float4(a0.y, a1.y, a2.y, a3.y);
            *(float4*)(out + (size_t)(rlo + 1) * D + lane * 4) = ohi;
        }
    }
}

// ---------------- launcher ----------------
extern "C" void kernel_launch(void* const* d_in, const int* in_sizes, int n_in,
                              void* d_out, int out_size) {
    const float* feat   = (const float*)d_in[0];
    const void*  src    = d_in[1];
    const void*  dst    = d_in[2];
    const float* Wself  = (const float*)d_in[3];
    const float* bself  = (const float*)d_in[4];
    const float* Wneigh = (const float*)d_in[5];
    const float* bias   = (const float*)d_in[6];
    float* out = (float*)d_out;

    cudaFuncSetAttribute(k_gemm, cudaFuncAttributeMaxDynamicSharedMemorySize,
                         (int)GEMM_SMEM);

    k_prep<<<(N_NODES + 255) / 256, 256>>>(Wself, bself, Wneigh, bias,
                                           (const unsigned*)src);
    k_hist<<<(N_EDGES + 255) / 256, 256>>>(dst);
    k_scan1<<<NBLK, SCAN_BLK>>>();
    k_scan2<<<1, 64>>>();
    k_scan3<<<NBLK, SCAN_BLK>>>();
    k_scatter<<<(N_EDGES + 255) / 256, 256>>>(src, dst);
    k_spmm<<<(N_NODES * 32 + 255) / 256, 256>>>(feat);
    k_gemm<<<(N_NODES + GROWS - 1) / GROWS, 256, GEMM_SMEM>>>(feat, out);
}

// round 6
// speedup vs baseline: 2.2731x; 2.0984x over previous
#include <cuda_runtime.h>
#include <cuda_bf16.h>
#include <cstdint>

#define N_NODES 50000
#define N_EDGES 800000
#define D 128
#define SCAN_BLK 1024
#define NBLK ((N_NODES + SCAN_BLK - 1) / SCAN_BLK)   // 49
#define MTILE 128
#define NTILES ((N_NODES + MTILE - 1) / MTILE)       // 391

// ---------------- device scratch ----------------
__device__ int   g_deg[N_NODES];
__device__ int   g_rowoff[N_NODES + 1];
__device__ int   g_cursor[N_NODES];
__device__ int   g_edgesrc[N_EDGES];
__device__ int   g_bsum[NBLK];
__device__ int   g_bpre[NBLK];
__device__ unsigned short g_Xhi[(size_t)N_NODES * 256];  // bf16 raw: [row][k], k<128 feat, k>=128 hneigh
__device__ unsigned short g_Xlo[(size_t)N_NODES * 256];
__device__ unsigned short g_Whi[128 * 256];              // [n][k]: k<128 Wself, k>=128 Wneigh
__device__ unsigned short g_Wlo[128 * 256];
__device__ float g_bcat[D];
__device__ int   g_is64;

// ---------------- small helpers ----------------
__device__ __forceinline__ int edge_idx(const void* p, int i, int is64) {
    return is64 ? (int)((const long long*)p)[i] : ((const int*)p)[i];
}
__device__ __forceinline__ void bf_split(float x, unsigned short& hi, unsigned short& lo) {
    __nv_bfloat16 h = __float2bfloat16_rn(x);
    hi = ((__nv_bfloat16_raw)h).x;
    float r = x - __bfloat162float(h);
    __nv_bfloat16 l = __float2bfloat16_rn(r);
    lo = ((__nv_bfloat16_raw)l).x;
}
__device__ __forceinline__ uint32_t smem_u32(const void* p) {
    uint32_t a;
    asm("{ .reg .u64 t; cvta.to.shared.u64 t, %1; cvt.u32.u64 %0, t; }" : "=r"(a) : "l"(p));
    return a;
}
// warp-level MMA primitives (sm_80 PTX — no 'a'-target features)
__device__ __forceinline__ void ldsm4(uint32_t* r, uint32_t addr) {
    asm volatile("ldmatrix.sync.aligned.m8n8.x4.shared.b16 {%0,%1,%2,%3}, [%4];"
        : "=r"(r[0]), "=r"(r[1]), "=r"(r[2]), "=r"(r[3]) : "r"(addr));
}
__device__ __forceinline__ void mma16816(float* d, const uint32_t* a, const uint32_t* b) {
    asm volatile(
        "mma.sync.aligned.m16n8k16.row.col.f32.bf16.bf16.f32 "
        "{%0,%1,%2,%3}, {%4,%5,%6,%7}, {%8,%9}, {%0,%1,%2,%3};"
        : "+f"(d[0]), "+f"(d[1]), "+f"(d[2]), "+f"(d[3])
        : "r"(a[0]), "r"(a[1]), "r"(a[2]), "r"(a[3]), "r"(b[0]), "r"(b[1]));
}

// ---------------- prep ----------------
__global__ void k_prep(const float* __restrict__ Wself, const float* __restrict__ bself,
                       const float* __restrict__ Wneigh, const float* __restrict__ bias,
                       const unsigned* __restrict__ src_raw) {
    int i = blockIdx.x * blockDim.x + threadIdx.x;
    if (blockIdx.x == 0) {                       // int64-vs-int32 detection
        __shared__ unsigned sor[8];
        int t = threadIdx.x, lane = t & 31, w = t >> 5;
        unsigned v = src_raw[2 * t + 1];
        #pragma unroll
        for (int off = 16; off > 0; off >>= 1) v |= __shfl_xor_sync(0xffffffffu, v, off);
        if (lane == 0) sor[w] = v;
        __syncthreads();
        if (t == 0) {
            unsigned o = 0;
            #pragma unroll
            for (int j = 0; j < 8; j++) o |= sor[j];
            g_is64 = (o == 0) ? 1 : 0;
            g_rowoff[N_NODES] = N_EDGES;
        }
    }
    if (i < N_NODES) { g_deg[i] = 0; g_cursor[i] = 0; }
    if (i < 128 * 256) {
        int n = i >> 8, k = i & 255;
        float w = (k < 128) ? Wself[n * 128 + k] : Wneigh[n * 128 + (k - 128)];
        unsigned short hi, lo;
        bf_split(w, hi, lo);
        g_Whi[i] = hi; g_Wlo[i] = lo;
    }
    if (i < D) g_bcat[i] = bself[i] + bias[i];
}

// feat -> Xhi/Xlo (k < 128)
__global__ void k_xfeat(const float* __restrict__ feat) {
    int t = blockIdx.x * blockDim.x + threadIdx.x;
    if (t >= N_NODES * 32) return;
    int row = t >> 5, c = t & 31;
    float4 f = *(const float4*)(feat + (size_t)row * D + c * 4);
    ushort4 h, l;
    bf_split(f.x, h.x, l.x); bf_split(f.y, h.y, l.y);
    bf_split(f.z, h.z, l.z); bf_split(f.w, h.w, l.w);
    size_t o = (size_t)row * 256 + c * 4;
    *(ushort4*)(g_Xhi + o) = h;
    *(ushort4*)(g_Xlo + o) = l;
}

// ---------------- CSR build ----------------
__global__ void k_hist(const void* __restrict__ dst) {
    int e = blockIdx.x * blockDim.x + threadIdx.x;
    if (e < N_EDGES) atomicAdd(&g_deg[edge_idx(dst, e, g_is64)], 1);
}

__global__ void k_scan1() {
    __shared__ int wsum[32];
    int t = threadIdx.x, lane = t & 31, w = t >> 5;
    int i = blockIdx.x * SCAN_BLK + t;
    int v = (i < N_NODES) ? g_deg[i] : 0;
    int x = v;
    #pragma unroll
    for (int off = 1; off < 32; off <<= 1) {
        int y = __shfl_up_sync(0xffffffff, x, off);
        if (lane >= off) x += y;
    }
    if (lane == 31) wsum[w] = x;
    __syncthreads();
    if (w == 0) {
        int s = wsum[lane];
        #pragma unroll
        for (int off = 1; off < 32; off <<= 1) {
            int y = __shfl_up_sync(0xffffffff, s, off);
            if (lane >= off) s += y;
        }
        wsum[lane] = s;
    }
    __syncthreads();
    int pre = (w > 0) ? wsum[w - 1] : 0;
    if (i < N_NODES) g_rowoff[i] = x + pre - v;       // block-local exclusive
    if (t == SCAN_BLK - 1) g_bsum[blockIdx.x] = x + pre;
}

__global__ void k_scan2() {
    __shared__ int ws[2];
    int t = threadIdx.x, lane = t & 31, w = t >> 5;
    int v = (t < NBLK) ? g_bsum[t] : 0;
    int x = v;
    #pragma unroll
    for (int off = 1; off < 32; off <<= 1) {
        int y = __shfl_up_sync(0xffffffff, x, off);
        if (lane >= off) x += y;
    }
    if (lane == 31) ws[w] = x;
    __syncthreads();
    if (w == 1) x += ws[0];
    if (t < NBLK) g_bpre[t] = x - v;
}

__global__ void k_scatter(const void* __restrict__ src, const void* __restrict__ dst) {
    int e = blockIdx.x * blockDim.x + threadIdx.x;
    if (e < N_EDGES) {
        int is64 = g_is64;
        int d = edge_idx(dst, e, is64);
        int s = edge_idx(src, e, is64);
        int base = g_rowoff[d] + g_bpre[d >> 10];
        g_edgesrc[base + atomicAdd(&g_cursor[d], 1)] = s;
    }
}

// ---------------- SpMM: warp per node, mean, writes bf16 hi/lo (k>=128) ----
__global__ void k_spmm(const float* __restrict__ feat) {
    int g = (blockIdx.x * blockDim.x + threadIdx.x) >> 5;
    int lane = threadIdx.x & 31;
    if (g >= N_NODES) return;
    int beg = g_rowoff[g] + g_bpre[g >> 10];
    int end = (g == N_NODES - 1) ? N_EDGES : g_rowoff[g + 1] + g_bpre[(g + 1) >> 10];
    float4 acc = make_float4(0.f, 0.f, 0.f, 0.f);
    int e = beg;
    for (; e + 3 < end; e += 4) {
        int s0 = g_edgesrc[e + 0], s1 = g_edgesrc[e + 1];
        int s2 = g_edgesrc[e + 2], s3 = g_edgesrc[e + 3];
        float4 f0 = *(const float4*)(feat + (size_t)s0 * D + lane * 4);
        float4 f1 = *(const float4*)(feat + (size_t)s1 * D + lane * 4);
        float4 f2 = *(const float4*)(feat + (size_t)s2 * D + lane * 4);
        float4 f3 = *(const float4*)(feat + (size_t)s3 * D + lane * 4);
        acc.x += f0.x + f1.x + f2.x + f3.x;
        acc.y += f0.y + f1.y + f2.y + f3.y;
        acc.z += f0.z + f1.z + f2.z + f3.z;
        acc.w += f0.w + f1.w + f2.w + f3.w;
    }
    for (; e < end; e++) {
        int s = g_edgesrc[e];
        float4 f = *(const float4*)(feat + (size_t)s * D + lane * 4);
        acc.x += f.x; acc.y += f.y; acc.z += f.z; acc.w += f.w;
    }
    float inv = (end > beg) ? 1.0f / (float)(end - beg) : 0.0f;
    acc.x *= inv; acc.y *= inv; acc.z *= inv; acc.w *= inv;
    ushort4 h, l;
    bf_split(acc.x, h.x, l.x); bf_split(acc.y, h.y, l.y);
    bf_split(acc.z, h.z, l.z); bf_split(acc.w, h.w, l.w);
    size_t o = (size_t)g * 256 + 128 + lane * 4;
    *(ushort4*)(g_Xhi + o) = h;
    *(ushort4*)(g_Xlo + o) = l;
}

// ---------------- HMMA bf16x3 GEMM: out = [feat|hneigh] @ W^T + bcat --------
// Block 256 thr / 8 warps. Tile 128 rows x 128 cols, K=256 in 4 phases of 64.
// smem: Ahi/Alo/Bhi/Blo, each 128 rows x 72 bf16 (pad 8) = 18KB -> 72KB total.
// Warp (wm 0..3, wn 0..1): 32 rows x 64 cols = 2 m16 x 8 n8 frags.
// Split product: D += Ahi*Bhi + Ahi*Blo + Alo*Bhi  (fp32 accum).
#define AS 72
#define GSMEM (4 * 128 * AS * 2)
__global__ void __launch_bounds__(256, 2) k_gemm_mma(float* __restrict__ out) {
    extern __shared__ unsigned short sm[];
    unsigned short* sAhi = sm;
    unsigned short* sAlo = sm + 128 * AS;
    unsigned short* sBhi = sm + 2 * 128 * AS;
    unsigned short* sBlo = sm + 3 * 128 * AS;
    int tid = threadIdx.x, wid = tid >> 5, l = tid & 31;
    int wm = wid >> 1, wn = wid & 1;
    int row0 = blockIdx.x * MTILE;

    float acc[2][8][4] = {};

    uint32_t sbase = smem_u32(sm);
    // ldmatrix per-lane addresses (bytes).
    // A x4: M0=(r0-7,k0-7) M1=(r8-15,k0-7) M2=(r0-7,k8-15) M3=(r8-15,k8-15)
    uint32_t aRow = (uint32_t)(wm * 32 + (l & 7) + ((l >> 3) & 1) * 8);
    uint32_t aK   = (uint32_t)((l >> 4) * 8);
    uint32_t aHi  = sbase + (aRow * AS + aK) * 2;
    uint32_t aLo  = aHi + 128 * AS * 2;
    // B x4 (2 n-tiles): M0=(n0-7,k0-7) M1=(n0-7,k8-15) M2=(n8-15,k0-7) M3=(n8-15,k8-15)
    uint32_t bRow = (uint32_t)(wn * 64 + (l & 7) + (l >> 4) * 8);
    uint32_t bK   = (uint32_t)(((l >> 3) & 1) * 8);
    uint32_t bHi  = sbase + 2 * 128 * AS * 2 + (bRow * AS + bK) * 2;
    uint32_t bLo  = bHi + 128 * AS * 2;

    #pragma unroll 1
    for (int ph = 0; ph < 4; ph++) {
        int kb = ph * 64;
        // stage 64-k slice of A(hi,lo) and B(hi,lo); coalesced 16B chunks
        for (int i = tid; i < 1024; i += 256) {
            int r = i >> 3, c = i & 7;
            int grow = row0 + r;
            uint4 vh = make_uint4(0u, 0u, 0u, 0u), vl = vh;
            if (grow < N_NODES) {
                vh = *(const uint4*)(g_Xhi + (size_t)grow * 256 + kb + c * 8);
                vl = *(const uint4*)(g_Xlo + (size_t)grow * 256 + kb + c * 8);
            }
            *(uint4*)(sAhi + r * AS + c * 8) = vh;
            *(uint4*)(sAlo + r * AS + c * 8) = vl;
            uint4 wh = *(const uint4*)(g_Whi + (size_t)r * 256 + kb + c * 8);
            uint4 wl = *(const uint4*)(g_Wlo + (size_t)r * 256 + kb + c * 8);
            *(uint4*)(sBhi + r * AS + c * 8) = wh;
            *(uint4*)(sBlo + r * AS + c * 8) = wl;
        }
        __syncthreads();
        #pragma unroll
        for (int ks = 0; ks < 4; ks++) {
            uint32_t ah[2][4], al[2][4];
            ldsm4(ah[0], aHi + ks * 32);
            ldsm4(ah[1], aHi + ks * 32 + 16 * AS * 2);
            ldsm4(al[0], aLo + ks * 32);
            ldsm4(al[1], aLo + ks * 32 + 16 * AS * 2);
            #pragma unroll
            for (int np = 0; np < 4; np++) {
                uint32_t bh[4], bl[4];
                ldsm4(bh, bHi + ks * 32 + np * 16 * AS * 2);
                ldsm4(bl, bLo + ks * 32 + np * 16 * AS * 2);
                #pragma unroll
                for (int mt = 0; mt < 2; mt++) {
                    mma16816(acc[mt][2 * np + 0], ah[mt], bh + 0);
                    mma16816(acc[mt][2 * np + 0], ah[mt], bl + 0);
                    mma16816(acc[mt][2 * np + 0], al[mt], bh + 0);
                    mma16816(acc[mt][2 * np + 1], ah[mt], bh + 2);
                    mma16816(acc[mt][2 * np + 1], ah[mt], bl + 2);
                    mma16816(acc[mt][2 * np + 1], al[mt], bh + 2);
                }
            }
        }
        __syncthreads();
    }

    // epilogue: c-frag lane l -> rows l/4 (+8), cols 2*(l%4) (+1)
    #pragma unroll
    for (int mt = 0; mt < 2; mt++) {
        #pragma unroll
        for (int half = 0; half < 2; half++) {
            int row = row0 + wm * 32 + mt * 16 + (l >> 2) + half * 8;
            if (row >= N_NODES) continue;
            #pragma unroll
            for (int nt = 0; nt < 8; nt++) {
                int col = wn * 64 + nt * 8 + (l & 3) * 2;
                float2 b = *(const float2*)(g_bcat + col);
                float2 o;
                o.x = acc[mt][nt][2 * half + 0] + b.x;
                o.y = acc[mt][nt][2 * half + 1] + b.y;
                *(float2*)(out + (size_t)row * D + col) = o;
            }
        }
    }
}

// ---------------- launcher ----------------
extern "C" void kernel_launch(void* const* d_in, const int* in_sizes, int n_in,
                              void* d_out, int out_size) {
    const float* feat   = (const float*)d_in[0];
    const void*  src    = d_in[1];
    const void*  dst    = d_in[2];
    const float* Wself  = (const float*)d_in[3];
    const float* bself  = (const float*)d_in[4];
    const float* Wneigh = (const float*)d_in[5];
    const float* bias   = (const float*)d_in[6];
    float* out = (float*)d_out;

    cudaFuncSetAttribute(k_gemm_mma, cudaFuncAttributeMaxDynamicSharedMemorySize, GSMEM);

    k_prep<<<(N_NODES + 255) / 256, 256>>>(Wself, bself, Wneigh, bias, (const unsigned*)src);
    k_xfeat<<<(N_NODES * 32 + 255) / 256, 256>>>(feat);
    k_hist<<<(N_EDGES + 255) / 256, 256>>>(dst);
    k_scan1<<<NBLK, SCAN_BLK>>>();
    k_scan2<<<1, 64>>>();
    k_scatter<<<(N_EDGES + 255) / 256, 256>>>(src, dst);
    k_spmm<<<(N_NODES * 32 + 255) / 256, 256>>>(feat);
    k_gemm_mma<<<NTILES, 256, GSMEM>>>(out);
}

// round 7
// speedup vs baseline: 2.4726x; 1.0878x over previous
#include <cuda_runtime.h>
#include <cuda_bf16.h>
#include <cstdint>

#define N_NODES 50000
#define N_EDGES 800000
#define D 128
#define SCAN_BLK 1024
#define NBLK ((N_NODES + SCAN_BLK - 1) / SCAN_BLK)   // 49
#define MTILE 128
#define NTILES ((N_NODES + MTILE - 1) / MTILE)       // 391

// ---------------- device scratch ----------------
__device__ int   g_deg[N_NODES];
__device__ int   g_rowoff[N_NODES + 1];
__device__ int   g_cursor[N_NODES];
__device__ int   g_edgesrc[N_EDGES];
__device__ int   g_bsum[NBLK];
__device__ int   g_bpre[NBLK];
__device__ int   g_scan_ctr = 0;
__device__ float g_hneigh[(size_t)N_NODES * D];          // fp32 mean-aggregated feats
__device__ unsigned short g_Whi[128 * 256];              // [n][k]: k<128 Wself, k>=128 Wneigh
__device__ unsigned short g_Wlo[128 * 256];
__device__ float g_bcat[D];
__device__ int   g_is64;

// ---------------- small helpers ----------------
__device__ __forceinline__ int edge_idx(const void* p, int i, int is64) {
    return is64 ? (int)((const long long*)p)[i] : ((const int*)p)[i];
}
__device__ __forceinline__ void bf_split(float x, unsigned short& hi, unsigned short& lo) {
    __nv_bfloat16 h = __float2bfloat16_rn(x);
    hi = ((__nv_bfloat16_raw)h).x;
    float r = x - __bfloat162float(h);
    __nv_bfloat16 l = __float2bfloat16_rn(r);
    lo = ((__nv_bfloat16_raw)l).x;
}
__device__ __forceinline__ uint32_t smem_u32(const void* p) {
    uint32_t a;
    asm("{ .reg .u64 t; cvta.to.shared.u64 t, %1; cvt.u32.u64 %0, t; }" : "=r"(a) : "l"(p));
    return a;
}
// warp-level MMA primitives (sm_80 PTX — safe for the harness's sm_103 ptxas target)
__device__ __forceinline__ void ldsm4(uint32_t* r, uint32_t addr) {
    asm volatile("ldmatrix.sync.aligned.m8n8.x4.shared.b16 {%0,%1,%2,%3}, [%4];"
        : "=r"(r[0]), "=r"(r[1]), "=r"(r[2]), "=r"(r[3]) : "r"(addr));
}
__device__ __forceinline__ void mma16816(float* d, const uint32_t* a, const uint32_t* b) {
    asm volatile(
        "mma.sync.aligned.m16n8k16.row.col.f32.bf16.bf16.f32 "
        "{%0,%1,%2,%3}, {%4,%5,%6,%7}, {%8,%9}, {%0,%1,%2,%3};"
        : "+f"(d[0]), "+f"(d[1]), "+f"(d[2]), "+f"(d[3])
        : "r"(a[0]), "r"(a[1]), "r"(a[2]), "r"(a[3]), "r"(b[0]), "r"(b[1]));
}

// ---------------- prep ----------------
__global__ void k_prep(const float* __restrict__ Wself, const float* __restrict__ bself,
                       const float* __restrict__ Wneigh, const float* __restrict__ bias,
                       const unsigned* __restrict__ src_raw) {
    int i = blockIdx.x * blockDim.x + threadIdx.x;
    if (blockIdx.x == 0) {                       // int64-vs-int32 detection
        __shared__ unsigned sor[8];
        int t = threadIdx.x, lane = t & 31, w = t >> 5;
        unsigned v = src_raw[2 * t + 1];
        #pragma unroll
        for (int off = 16; off > 0; off >>= 1) v |= __shfl_xor_sync(0xffffffffu, v, off);
        if (lane == 0) sor[w] = v;
        __syncthreads();
        if (t == 0) {
            unsigned o = 0;
            #pragma unroll
            for (int j = 0; j < 8; j++) o |= sor[j];
            g_is64 = (o == 0) ? 1 : 0;
            g_rowoff[N_NODES] = N_EDGES;
            g_scan_ctr = 0;
        }
    }
    if (i < N_NODES) { g_deg[i] = 0; g_cursor[i] = 0; }
    if (i < 128 * 256) {
        int n = i >> 8, k = i & 255;
        float w = (k < 128) ? Wself[n * 128 + k] : Wneigh[n * 128 + (k - 128)];
        unsigned short hi, lo;
        bf_split(w, hi, lo);
        g_Whi[i] = hi; g_Wlo[i] = lo;
    }
    if (i < D) g_bcat[i] = bself[i] + bias[i];
}

// ---------------- CSR build ----------------
__global__ void k_hist(const void* __restrict__ dst) {
    int e = blockIdx.x * blockDim.x + threadIdx.x;
    if (e < N_EDGES) atomicAdd(&g_deg[edge_idx(dst, e, g_is64)], 1);
}

// block-level exclusive scan + last-block scans the 49 partials (kills scan2)
__global__ void k_scan1() {
    __shared__ int wsum[32];
    __shared__ int s_last;
    int t = threadIdx.x, lane = t & 31, w = t >> 5;
    int i = blockIdx.x * SCAN_BLK + t;
    int v = (i < N_NODES) ? g_deg[i] : 0;
    int x = v;
    #pragma unroll
    for (int off = 1; off < 32; off <<= 1) {
        int y = __shfl_up_sync(0xffffffff, x, off);
        if (lane >= off) x += y;
    }
    if (lane == 31) wsum[w] = x;
    __syncthreads();
    if (w == 0) {
        int s = wsum[lane];
        #pragma unroll
        for (int off = 1; off < 32; off <<= 1) {
            int y = __shfl_up_sync(0xffffffff, s, off);
            if (lane >= off) s += y;
        }
        wsum[lane] = s;
    }
    __syncthreads();
    int pre = (w > 0) ? wsum[w - 1] : 0;
    if (i < N_NODES) g_rowoff[i] = x + pre - v;       // block-local exclusive
    if (t == SCAN_BLK - 1) g_bsum[blockIdx.x] = x + pre;
    // last arriving block scans the block sums
    if (t == 0) {
        __threadfence();
        s_last = (atomicAdd(&g_scan_ctr, 1) == NBLK - 1) ? 1 : 0;
    }
    __syncthreads();
    if (s_last) {
        __shared__ int ws2[2];
        if (t < 64) {
            int v2 = (t < NBLK) ? g_bsum[t] : 0;
            int x2 = v2;
            #pragma unroll
            for (int off = 1; off < 32; off <<= 1) {
                int y = __shfl_up_sync(0xffffffff, x2, off);
                if (lane >= off) x2 += y;
            }
            if (lane == 31) ws2[w] = x2;
            __syncthreads();
            if (w == 1) x2 += ws2[0];
            if (t < NBLK) g_bpre[t] = x2 - v2;
        } else {
            __syncthreads();
        }
        if (t == 0) g_scan_ctr = 0;                   // reset for next replay
    }
}

__global__ void k_scatter(const void* __restrict__ src, const void* __restrict__ dst) {
    int e = blockIdx.x * blockDim.x + threadIdx.x;
    if (e < N_EDGES) {
        int is64 = g_is64;
        int d = edge_idx(dst, e, is64);
        int s = edge_idx(src, e, is64);
        int base = g_rowoff[d] + g_bpre[d >> 10];
        g_edgesrc[base + atomicAdd(&g_cursor[d], 1)] = s;
    }
}

// ---------------- SpMM: warp per node, gather + mean, fp32 out -------------
__global__ void k_spmm(const float* __restrict__ feat) {
    int g = (blockIdx.x * blockDim.x + threadIdx.x) >> 5;
    int lane = threadIdx.x & 31;
    if (g >= N_NODES) return;
    int beg = g_rowoff[g] + g_bpre[g >> 10];
    int end = (g == N_NODES - 1) ? N_EDGES : g_rowoff[g + 1] + g_bpre[(g + 1) >> 10];
    float4 acc = make_float4(0.f, 0.f, 0.f, 0.f);
    int e = beg;
    for (; e + 7 < end; e += 8) {                    // 8 outstanding LDG.128/lane
        float4 f[8];
        #pragma unroll
        for (int j = 0; j < 8; j++) {
            int s = g_edgesrc[e + j];
            f[j] = *(const float4*)(feat + (size_t)s * D + lane * 4);
        }
        #pragma unroll
        for (int j = 0; j < 8; j++) {
            acc.x += f[j].x; acc.y += f[j].y; acc.z += f[j].z; acc.w += f[j].w;
        }
    }
    for (; e < end; e++) {
        int s = g_edgesrc[e];
        float4 f = *(const float4*)(feat + (size_t)s * D + lane * 4);
        acc.x += f.x; acc.y += f.y; acc.z += f.z; acc.w += f.w;
    }
    float inv = (end > beg) ? 1.0f / (float)(end - beg) : 0.0f;
    acc.x *= inv; acc.y *= inv; acc.z *= inv; acc.w *= inv;
    *(float4*)(g_hneigh + (size_t)g * D + lane * 4) = acc;
}

// ---------------- HMMA bf16x3 GEMM: out = [feat|hneigh] @ W^T + bcat --------
// Block 256 thr / 8 warps. Tile 128 rows x 128 cols, K=256 in 4 phases of 64.
// A staged from fp32 (feat: phases 0-1, hneigh: phases 2-3) with inline
// hi/lo bf16 split. smem: Ahi/Alo/Bhi/Blo @ 128 x 72 bf16 -> 72KB total.
// Split product: D += Ahi*Bhi + Ahi*Blo + Alo*Bhi  (fp32 accum).
#define AS 72
#define GSMEM (4 * 128 * AS * 2)
__global__ void __launch_bounds__(256, 2) k_gemm_mma(const float* __restrict__ feat,
                                                     float* __restrict__ out) {
    extern __shared__ unsigned short sm[];
    unsigned short* sAhi = sm;
    unsigned short* sAlo = sm + 128 * AS;
    unsigned short* sBhi = sm + 2 * 128 * AS;
    unsigned short* sBlo = sm + 3 * 128 * AS;
    int tid = threadIdx.x, l = tid & 31, wid = tid >> 5;
    int wm = wid >> 1, wn = wid & 1;
    int row0 = blockIdx.x * MTILE;

    float acc[2][8][4] = {};

    uint32_t sbase = smem_u32(sm);
    uint32_t aRow = (uint32_t)(wm * 32 + (l & 7) + ((l >> 3) & 1) * 8);
    uint32_t aK   = (uint32_t)((l >> 4) * 8);
    uint32_t aHi  = sbase + (aRow * AS + aK) * 2;
    uint32_t aLo  = aHi + 128 * AS * 2;
    uint32_t bRow = (uint32_t)(wn * 64 + (l & 7) + (l >> 4) * 8);
    uint32_t bK   = (uint32_t)(((l >> 3) & 1) * 8);
    uint32_t bHi  = sbase + 2 * 128 * AS * 2 + (bRow * AS + bK) * 2;
    uint32_t bLo  = bHi + 128 * AS * 2;

    #pragma unroll 1
    for (int ph = 0; ph < 4; ph++) {
        int kb = ph * 64;
        const float* srcA = (ph < 2) ? (feat + ph * 64)
                                     : (g_hneigh + (ph - 2) * 64);
        // stage A: 128 rows x 64 k fp32 -> split into hi/lo bf16
        for (int i = tid; i < 2048; i += 256) {       // float4 units
            int r = i >> 4, c = i & 15;
            int grow = row0 + r;
            float4 f = make_float4(0.f, 0.f, 0.f, 0.f);
            if (grow < N_NODES)
                f = *(const float4*)(srcA + (size_t)grow * D + c * 4);
            ushort4 h, lo4;
            bf_split(f.x, h.x, lo4.x); bf_split(f.y, h.y, lo4.y);
            bf_split(f.z, h.z, lo4.z); bf_split(f.w, h.w, lo4.w);
            *(ushort4*)(sAhi + r * AS + c * 4) = h;
            *(ushort4*)(sAlo + r * AS + c * 4) = lo4;
        }
        // stage B: 128 rows x 64 k bf16 hi/lo
        for (int i = tid; i < 1024; i += 256) {       // uint4 units (8 bf16)
            int r = i >> 3, c = i & 7;
            *(uint4*)(sBhi + r * AS + c * 8) =
                *(const uint4*)(g_Whi + (size_t)r * 256 + kb + c * 8);
            *(uint4*)(sBlo + r * AS + c * 8) =
                *(const uint4*)(g_Wlo + (size_t)r * 256 + kb + c * 8);
        }
        __syncthreads();
        #pragma unroll
        for (int ks = 0; ks < 4; ks++) {
            uint32_t ah[2][4], al[2][4];
            ldsm4(ah[0], aHi + ks * 32);
            ldsm4(ah[1], aHi + ks * 32 + 16 * AS * 2);
            ldsm4(al[0], aLo + ks * 32);
            ldsm4(al[1], aLo + ks * 32 + 16 * AS * 2);
            #pragma unroll
            for (int np = 0; np < 4; np++) {
                uint32_t bh[4], bl[4];
                ldsm4(bh, bHi + ks * 32 + np * 16 * AS * 2);
                ldsm4(bl, bLo + ks * 32 + np * 16 * AS * 2);
                #pragma unroll
                for (int mt = 0; mt < 2; mt++) {
                    mma16816(acc[mt][2 * np + 0], ah[mt], bh + 0);
                    mma16816(acc[mt][2 * np + 0], ah[mt], bl + 0);
                    mma16816(acc[mt][2 * np + 0], al[mt], bh + 0);
                    mma16816(acc[mt][2 * np + 1], ah[mt], bh + 2);
                    mma16816(acc[mt][2 * np + 1], ah[mt], bl + 2);
                    mma16816(acc[mt][2 * np + 1], al[mt], bh + 2);
                }
            }
        }
        __syncthreads();
    }

    // epilogue: c-frag lane l -> rows l/4 (+8), cols 2*(l%4) (+1)
    #pragma unroll
    for (int mt = 0; mt < 2; mt++) {
        #pragma unroll
        for (int half = 0; half < 2; half++) {
            int row = row0 + wm * 32 + mt * 16 + (l >> 2) + half * 8;
            if (row >= N_NODES) continue;
            #pragma unroll
            for (int nt = 0; nt < 8; nt++) {
                int col = wn * 64 + nt * 8 + (l & 3) * 2;
                float2 b = *(const float2*)(g_bcat + col);
                float2 o;
                o.x = acc[mt][nt][2 * half + 0] + b.x;
                o.y = acc[mt][nt][2 * half + 1] + b.y;
                *(float2*)(out + (size_t)row * D + col) = o;
            }
        }
    }
}

// ---------------- launcher ----------------
extern "C" void kernel_launch(void* const* d_in, const int* in_sizes, int n_in,
                              void* d_out, int out_size) {
    const float* feat   = (const float*)d_in[0];
    const void*  src    = d_in[1];
    const void*  dst    = d_in[2];
    const float* Wself  = (const float*)d_in[3];
    const float* bself  = (const float*)d_in[4];
    const float* Wneigh = (const float*)d_in[5];
    const float* bias   = (const float*)d_in[6];
    float* out = (float*)d_out;

    cudaFuncSetAttribute(k_gemm_mma, cudaFuncAttributeMaxDynamicSharedMemorySize, GSMEM);

    k_prep<<<(N_NODES + 255) / 256, 256>>>(Wself, bself, Wneigh, bias, (const unsigned*)src);
    k_hist<<<(N_EDGES + 255) / 256, 256>>>(dst);
    k_scan1<<<NBLK, SCAN_BLK>>>();
    k_scatter<<<(N_EDGES + 255) / 256, 256>>>(src, dst);
    k_spmm<<<(N_NODES * 32 + 255) / 256, 256>>>(feat);
    k_gemm_mma<<<NTILES, 256, GSMEM>>>(feat, out);
}